// round 6
// baseline (speedup 1.0000x reference)
#include <cuda_runtime.h>
#include <cstdint>
#include <cstddef>

#define Bsz 64
#define Ssz 2048
#define Isz 256
#define Hsz 512

// Scratch for precomputed input projections, laid out [S][B][H] so the
// recurrent kernel reads one contiguous 128KB slab per step.
__device__ float g_xproj[(size_t)Ssz * Bsz * Hsz];

__device__ __forceinline__ uint32_t smem_u32(const void* p) {
    return (uint32_t)__cvta_generic_to_shared(p);
}

__device__ __forceinline__ void cluster_sync_() {
    asm volatile("barrier.cluster.arrive.aligned;" ::: "memory");
    asm volatile("barrier.cluster.wait.aligned;" ::: "memory");
}

__device__ __forceinline__ void dsmem_store_f32(uint32_t laddr, uint32_t rank, float v) {
    uint32_t raddr;
    asm volatile("mapa.shared::cluster.u32 %0, %1, %2;"
                 : "=r"(raddr) : "r"(laddr), "r"(rank));
    asm volatile("st.shared::cluster.f32 [%0], %1;"
                 :: "r"(raddr), "f"(v) : "memory");
}

// ---------------------------------------------------------------------------
// Phase 1: xproj[s][b][h] = sum_i x[b][s][i] * W_ih[h][i] + b_ih[h] + b_hh[h]
// Tile: 128 (s) x 64 (h), K-chunks of 32, 256 threads, 8x4 register blocking.
// ---------------------------------------------------------------------------
__global__ __launch_bounds__(256) void xproj_kernel(
    const float* __restrict__ x, const float* __restrict__ Wih,
    const float* __restrict__ bih, const float* __restrict__ bhh) {
    __shared__ float xs[32][132];  // [k][m], padded
    __shared__ float ws[32][68];   // [k][h], padded

    const int b  = blockIdx.z;
    const int s0 = blockIdx.y * 128;
    const int h0 = blockIdx.x * 64;
    const int tid = threadIdx.x;
    const int tx = tid & 15;   // h groups of 4
    const int ty = tid >> 4;   // s groups of 8

    const float* xbase = x + ((size_t)b * Ssz + s0) * Isz;
    const float* wbase = Wih + (size_t)h0 * Isz;

    const int xrow = tid >> 1;        // 0..127
    const int xkh  = (tid & 1) * 16;  // 0 or 16
    const int wrow = tid >> 2;        // 0..63
    const int wkh  = (tid & 3) * 8;   // 0,8,16,24

    float acc[8][4];
#pragma unroll
    for (int i = 0; i < 8; i++)
#pragma unroll
        for (int j = 0; j < 4; j++) acc[i][j] = 0.f;

    for (int k0 = 0; k0 < Isz; k0 += 32) {
#pragma unroll
        for (int q = 0; q < 4; q++) {
            float4 v = *(const float4*)&xbase[(size_t)xrow * Isz + k0 + xkh + q * 4];
            xs[xkh + q * 4 + 0][xrow] = v.x;
            xs[xkh + q * 4 + 1][xrow] = v.y;
            xs[xkh + q * 4 + 2][xrow] = v.z;
            xs[xkh + q * 4 + 3][xrow] = v.w;
        }
#pragma unroll
        for (int q = 0; q < 2; q++) {
            float4 v = *(const float4*)&wbase[(size_t)wrow * Isz + k0 + wkh + q * 4];
            ws[wkh + q * 4 + 0][wrow] = v.x;
            ws[wkh + q * 4 + 1][wrow] = v.y;
            ws[wkh + q * 4 + 2][wrow] = v.z;
            ws[wkh + q * 4 + 3][wrow] = v.w;
        }
        __syncthreads();
#pragma unroll 8
        for (int k = 0; k < 32; k++) {
            float4 a0 = *(const float4*)&xs[k][ty * 8];
            float4 a1 = *(const float4*)&xs[k][ty * 8 + 4];
            float4 wv = *(const float4*)&ws[k][tx * 4];
            float av[8] = {a0.x, a0.y, a0.z, a0.w, a1.x, a1.y, a1.z, a1.w};
            float wl[4] = {wv.x, wv.y, wv.z, wv.w};
#pragma unroll
            for (int i = 0; i < 8; i++)
#pragma unroll
                for (int j = 0; j < 4; j++)
                    acc[i][j] = fmaf(av[i], wl[j], acc[i][j]);
        }
        __syncthreads();
    }

    float bias[4];
#pragma unroll
    for (int j = 0; j < 4; j++)
        bias[j] = bih[h0 + tx * 4 + j] + bhh[h0 + tx * 4 + j];

#pragma unroll
    for (int i = 0; i < 8; i++) {
        int s = s0 + ty * 8 + i;
        float4 o = make_float4(acc[i][0] + bias[0], acc[i][1] + bias[1],
                               acc[i][2] + bias[2], acc[i][3] + bias[3]);
        *(float4*)&g_xproj[(size_t)s * (Bsz * Hsz) + (size_t)b * Hsz + h0 + tx * 4] = o;
    }
}

// ---------------------------------------------------------------------------
// Phase 2: persistent clustered recurrence.
// 16 clusters x 8 CTAs. Cluster c owns batches [4c, 4c+4). CTA rank rk owns
// W_hh rows [64rk, 64rk+64) entirely in registers (thread: 4 rows x 32 K).
// Per step: FFMA (2048cyc floor) -> smem K-reduction -> tanh -> DSMEM
// broadcast of the new h chunk to all 8 CTAs -> cluster barrier.
// ---------------------------------------------------------------------------
__global__ __launch_bounds__(256, 1) __cluster_dims__(8, 1, 1)
void rnn_kernel(const float* __restrict__ Whh, float* __restrict__ out) {
    __shared__ float  hbuf[2][4][Hsz];   // double-buffered full h (replicated)
    __shared__ float4 red[16][4][16];    // [kslice][batch][rowgrp] partials

    const int tid = threadIdx.x;
    const int rk  = blockIdx.x & 7;          // cluster rank -> row slab
    const int b0  = (blockIdx.x >> 3) * 4;   // first batch of this cluster
    const int kc  = tid >> 4;                // K-slice 0..15 (32 K each)
    const int rg  = tid & 15;                // row group 0..15 (4 rows each)

    // Resident W_hh slab: rows rk*64 + rg*4 + i, cols kc*32 + 4*jq + {0..3}
    float4 w[4][8];
#pragma unroll
    for (int i = 0; i < 4; i++)
#pragma unroll
        for (int jq = 0; jq < 8; jq++)
            w[i][jq] = *(const float4*)&Whh[(size_t)(rk * 64 + rg * 4 + i) * Hsz +
                                            kc * 32 + jq * 4];

    // h0 = 0
    for (int idx = tid; idx < 2 * 4 * Hsz; idx += 256)
        ((float*)hbuf)[idx] = 0.f;
    __syncthreads();
    cluster_sync_();

    // Reduction-phase thread mapping: one output (batch b2, row r2) per thread
    const int b2   = tid >> 6;      // 0..3
    const int r2   = tid & 63;      // 0..63
    const int hout = rk * 64 + r2;  // global h index this thread produces
    float* outp = out + (size_t)(b0 + b2) * Ssz * Hsz + hout;
    const float* xpp = g_xproj + (size_t)(b0 + b2) * Hsz + hout;
    const uint32_t dst0 = smem_u32(&hbuf[0][b2][hout]);
    const uint32_t bufbytes = 4 * Hsz * sizeof(float);  // hbuf[0] -> hbuf[1]

    int cur = 0;
    for (int s = 0; s < Ssz; s++) {
        float xp = xpp[(size_t)s * (Bsz * Hsz)];  // issued early, used late

        float acc[4][4];
#pragma unroll
        for (int b = 0; b < 4; b++)
#pragma unroll
            for (int i = 0; i < 4; i++) acc[b][i] = 0.f;

#pragma unroll
        for (int b = 0; b < 4; b++) {
            const float* hb = &hbuf[cur][b][kc * 32];
#pragma unroll
            for (int jq = 0; jq < 8; jq++) {
                float4 hv = *(const float4*)&hb[jq * 4];
#pragma unroll
                for (int i = 0; i < 4; i++) {
                    acc[b][i] = fmaf(w[i][jq].x, hv.x, acc[b][i]);
                    acc[b][i] = fmaf(w[i][jq].y, hv.y, acc[b][i]);
                    acc[b][i] = fmaf(w[i][jq].z, hv.z, acc[b][i]);
                    acc[b][i] = fmaf(w[i][jq].w, hv.w, acc[b][i]);
                }
            }
        }

#pragma unroll
        for (int b = 0; b < 4; b++)
            red[kc][b][rg] = make_float4(acc[b][0], acc[b][1], acc[b][2], acc[b][3]);
        __syncthreads();

        // K-slice reduction for this thread's output
        const float* redf = (const float*)red;
        float part[16];
#pragma unroll
        for (int k = 0; k < 16; k++)
            part[k] = redf[k * 256 + b2 * 64 + r2];
        float sum = xp;
#pragma unroll
        for (int k = 0; k < 16; k++) sum += part[k];

        float hn = tanhf(sum);
        outp[(size_t)s * Hsz] = hn;

        // Broadcast new h element into every cluster CTA's next buffer
        const uint32_t dst = dst0 + (uint32_t)(cur ^ 1) * bufbytes;
#pragma unroll
        for (int p = 0; p < 8; p++) dsmem_store_f32(dst, (uint32_t)p, hn);

        cluster_sync_();  // also acts as the CTA barrier protecting 'red'
        cur ^= 1;
    }
}

extern "C" void kernel_launch(void* const* d_in, const int* in_sizes, int n_in,
                              void* d_out, int out_size) {
    const float* x   = (const float*)d_in[0];
    const float* Wih = (const float*)d_in[1];
    const float* Whh = (const float*)d_in[2];
    const float* bih = (const float*)d_in[3];
    const float* bhh = (const float*)d_in[4];
    float* out = (float*)d_out;
    (void)in_sizes; (void)n_in; (void)out_size;

    dim3 g1(Hsz / 64, Ssz / 128, Bsz);
    xproj_kernel<<<g1, 256>>>(x, Wih, bih, bhh);
    rnn_kernel<<<128, 256>>>(Whh, out);
}